// round 4
// baseline (speedup 1.0000x reference)
#include <cuda_runtime.h>

#define B_    32768
#define W_    5
#define L_    20
#define CE_   32
#define OC_   30
#define WE_   50
#define HID_  100
#define TAGS_ 36
#define FEAT_ 400
#define TPOS  18

typedef unsigned long long ull;

__device__ float g_feats[B_ * FEAT_];
__device__ float g_Pk[3 * 100 * 32];     // [k][c][oc], oc padded to 32 (zeros)

// ---------------- packed fp32x2 helpers ----------------
__device__ __forceinline__ ull ffma2(ull a, ull b, ull c) {
    ull d;
    asm("fma.rn.f32x2 %0, %1, %2, %3;" : "=l"(d) : "l"(a), "l"(b), "l"(c));
    return d;
}
__device__ __forceinline__ ull add2(ull a, ull b) {
    ull d;
    asm("add.rn.f32x2 %0, %1, %2;" : "=l"(d) : "l"(a), "l"(b));
    return d;
}
__device__ __forceinline__ ull pack2(float lo, float hi) {
    ull r;
    asm("mov.b64 %0, {%1, %2};"
        : "=l"(r) : "r"(__float_as_uint(lo)), "r"(__float_as_uint(hi)));
    return r;
}
__device__ __forceinline__ void unpack2(ull v, float& lo, float& hi) {
    unsigned int a, b;
    asm("mov.b64 {%0, %1}, %2;" : "=r"(a), "=r"(b) : "l"(v));
    lo = __uint_as_float(a);
    hi = __uint_as_float(b);
}

// ---------------- Kernel 0: P[k][c][oc] = sum_ce convw[oc][ce][k] * cemb[c][ce] ------
__global__ void prep_kernel(const float* __restrict__ cemb,
                            const float* __restrict__ convw)
{
    const int idx = blockIdx.x * 256 + threadIdx.x;
    if (idx >= 9600) return;
    const int k  = idx / 3200;
    const int r  = idx - k * 3200;
    const int c  = r >> 5;
    const int oc = r & 31;
    float s = 0.f;
    if (oc < OC_) {
        const float* wr = convw + oc * (CE_ * 3) + k;
        const float* er = cemb + c * CE_;
#pragma unroll
        for (int ce = 0; ce < CE_; ++ce) s = fmaf(wr[ce * 3], er[ce], s);
    }
    g_Pk[idx] = s;
}

// ---------------- Kernel 1: conv via table + maxpool + word-emb gather --------------
// Two words per warp (half-warps); lane handles an oc-PAIR in f32x2.
__global__ __launch_bounds__(256, 4)
void conv_kernel(const int* __restrict__ inp,
                 const float* __restrict__ wemb,
                 const float* __restrict__ convb)
{
    __shared__ __align__(16) float P_sh[9600];    // 38.4 KB
    __shared__ __align__(8)  float2 b2_sh[16];

    const int tid  = threadIdx.x;
    const int warp = tid >> 5;
    const int lane = tid & 31;

    for (int i = tid; i < 9600; i += 256) P_sh[i] = g_Pk[i];
    if (tid < 16) {
        float2 bb = make_float2(0.f, 0.f);
        if (tid < 15) bb = make_float2(convb[2 * tid], convb[2 * tid + 1]);
        b2_sh[tid] = bb;
    }
    __syncthreads();

    const float* __restrict__ P0 = P_sh;
    const float* __restrict__ P1 = P_sh + 3200;
    const float* __restrict__ P2 = P_sh + 6400;

    const int half = lane >> 4;        // 0 = word A, 1 = word B
    const int ocp  = lane & 15;        // oc-pair index; valid < 15

    for (int it = 0; it < 16; ++it) {
        const int gwA = blockIdx.x * 256 + it * 16 + warp * 2;
        const int* __restrict__ rowp = inp + gwA * (1 + L_);
        const int v  = (lane < 21) ? rowp[lane]      : 0;
        const int v2 = (lane < 21) ? rowp[21 + lane] : 0;

        ull acc[TPOS];
#pragma unroll
        for (int t = 0; t < TPOS; ++t) acc[t] = 0ull;

#pragma unroll
        for (int l = 0; l < L_; ++l) {
            const int cA = __shfl_sync(0xffffffffu, v,  l + 1);
            const int cB = __shfl_sync(0xffffffffu, v2, l + 1);
            const int c  = half ? cB : cA;
            const int base = c * 32 + ocp * 2;
            const ull x0 = *(const ull*)&P0[base];
            const ull x1 = *(const ull*)&P1[base];
            const ull x2 = *(const ull*)&P2[base];
            if (l < TPOS)             acc[l]     = add2(acc[l],     x0);
            if (l >= 1 && l <= TPOS)  acc[l - 1] = add2(acc[l - 1], x1);
            if (l >= 2)               acc[l - 2] = add2(acc[l - 2], x2);
        }

        float m0, m1;
        unpack2(acc[0], m0, m1);
#pragma unroll
        for (int t = 1; t < TPOS; ++t) {
            float a, b;
            unpack2(acc[t], a, b);
            m0 = fmaxf(m0, a);
            m1 = fmaxf(m1, b);
        }

        const int gw = gwA + half;
        const int bI = gw / W_;
        const int wi = gw - bI * W_;
        float* __restrict__ fout = g_feats + bI * FEAT_ + wi * (WE_ + OC_);
        if (ocp < 15) {
            const float2 bb = b2_sh[ocp];
            *(ull*)&fout[WE_ + 2 * ocp] = pack2(m0 + bb.x, m1 + bb.y);
        }

        // word-embedding gather for both words (full warp each)
        const int widA = __shfl_sync(0xffffffffu, v,  0);
        const int widB = __shfl_sync(0xffffffffu, v2, 0);
        const int bA = gwA / W_, wiA = gwA - bA * W_;
        const int gwB = gwA + 1;
        const int bB = gwB / W_, wiB = gwB - bB * W_;
        float* __restrict__ fA = g_feats + bA * FEAT_ + wiA * (WE_ + OC_);
        float* __restrict__ fB = g_feats + bB * FEAT_ + wiB * (WE_ + OC_);
        const float* __restrict__ eA = wemb + widA * WE_;
        const float* __restrict__ eB = wemb + widB * WE_;
        fA[lane] = eA[lane];
        fB[lane] = eB[lane];
        if (lane < WE_ - 32) {
            fA[32 + lane] = eA[32 + lane];
            fB[32 + lane] = eB[32 + lane];
        }
    }
}

// ---------------- Kernel 2: fc1 + tanh + out ----------------------------------------
// 13 warps: warp = 8-j tile (broadcast weight loads), lane = sample-pair.
#define MT 64
#define KC 40

__global__ __launch_bounds__(416, 2)
void fc_kernel(const float* __restrict__ fc1w, const float* __restrict__ fc1b,
               const float* __restrict__ outw, const float* __restrict__ outb,
               float* __restrict__ out)
{
    __shared__ __align__(16) float pool[10880];    // fsh[40][64] + wsh[40][208] ; hT[104][64] reuse
    __shared__ __align__(16) float owd[100 * 72];  // out weights duplicated [j][2*tag]
    __shared__ float b_sh[104];
    __shared__ float ob_sh[TAGS_];

    float* fsh = pool;             // stride 64
    float* wsh = pool + 2560;      // stride 208
    float* hT  = pool;             // [j][64] after main loop

    const int tid  = threadIdx.x;
    const int warp = tid >> 5;
    const int lane = tid & 31;
    const int s0   = blockIdx.x * MT;

    for (int i = tid; i < TAGS_ * HID_; i += 416) {
        const int t = i / HID_;
        const int j = i - t * HID_;
        const float w = outw[i];
        owd[j * 72 + 2 * t]     = w;
        owd[j * 72 + 2 * t + 1] = w;
    }
    if (tid < 104) b_sh[tid] = (tid < HID_) ? fc1b[tid] : 0.f;
    if (tid < TAGS_) ob_sh[tid] = outb[tid];

    ull acc[8];
#pragma unroll
    for (int p = 0; p < 8; ++p) acc[p] = 0ull;

    for (int kc = 0; kc < FEAT_ / KC; ++kc) {
        const int k0 = kc * KC;
        __syncthreads();
        for (int i = tid; i < KC * MT; i += 416) {          // feats [k][s]
            const int k = i % KC;
            const int s = i / KC;
            fsh[k * 64 + s] = g_feats[(s0 + s) * FEAT_ + k0 + k];
        }
        for (int i = tid; i < KC * 104; i += 416) {         // weights duplicated [k][2j]
            const int k = i % KC;
            const int j = i / KC;
            const float w = (j < HID_) ? fc1w[j * FEAT_ + k0 + k] : 0.f;
            *(ull*)&wsh[k * 208 + 2 * j] = pack2(w, w);
        }
        __syncthreads();

#pragma unroll 4
        for (int k = 0; k < KC; ++k) {
            const float* wrow = &wsh[k * 208 + warp * 16];   // lane-invariant (broadcast)
            const ulonglong2 wa = *(const ulonglong2*)(wrow);
            const ulonglong2 wb = *(const ulonglong2*)(wrow + 4);
            const ulonglong2 wc = *(const ulonglong2*)(wrow + 8);
            const ulonglong2 wd = *(const ulonglong2*)(wrow + 12);
            const ull f = *(const ull*)&fsh[k * 64 + 2 * lane];
            acc[0] = ffma2(f, wa.x, acc[0]);
            acc[1] = ffma2(f, wa.y, acc[1]);
            acc[2] = ffma2(f, wb.x, acc[2]);
            acc[3] = ffma2(f, wb.y, acc[3]);
            acc[4] = ffma2(f, wc.x, acc[4]);
            acc[5] = ffma2(f, wc.y, acc[5]);
            acc[6] = ffma2(f, wd.x, acc[6]);
            acc[7] = ffma2(f, wd.y, acc[7]);
        }
    }
    __syncthreads();

    // tanh + transpose into hT[j][s]
    const int j0 = warp * 8;
#pragma unroll
    for (int jj = 0; jj < 8; ++jj) {
        float a, c;
        unpack2(acc[jj], a, c);
        const float bb = b_sh[j0 + jj];
        *(ull*)&hT[(j0 + jj) * 64 + 2 * lane] = pack2(tanhf(a + bb), tanhf(c + bb));
    }
    __syncthreads();

    // out layer: warp = 4 tags (broadcast weights), lane = sample-pair
    if (warp < 9) {
        const int t0 = warp * 4;
        ull a4[4];
#pragma unroll
        for (int p = 0; p < 4; ++p) a4[p] = 0ull;
#pragma unroll 4
        for (int j = 0; j < HID_; ++j) {
            const ull h = *(const ull*)&hT[j * 64 + 2 * lane];
            const ulonglong2 w01 = *(const ulonglong2*)&owd[j * 72 + 2 * t0];
            const ulonglong2 w23 = *(const ulonglong2*)&owd[j * 72 + 2 * t0 + 4];
            a4[0] = ffma2(h, w01.x, a4[0]);
            a4[1] = ffma2(h, w01.y, a4[1]);
            a4[2] = ffma2(h, w23.x, a4[2]);
            a4[3] = ffma2(h, w23.y, a4[3]);
        }
        float* op = out + (s0 + 2 * lane) * TAGS_ + t0;
#pragma unroll
        for (int tt = 0; tt < 4; ++tt) {
            float a, c;
            unpack2(a4[tt], a, c);
            const float bo = ob_sh[t0 + tt];
            op[tt]         = a + bo;
            op[TAGS_ + tt] = c + bo;
        }
    }
}

// ---------------- launch ----------------
extern "C" void kernel_launch(void* const* d_in, const int* in_sizes, int n_in,
                              void* d_out, int out_size)
{
    const int*   inp   = (const int*)  d_in[0];
    const float* wemb  = (const float*)d_in[1];
    const float* cemb  = (const float*)d_in[2];
    const float* convw = (const float*)d_in[3];
    const float* convb = (const float*)d_in[4];
    const float* fc1w  = (const float*)d_in[5];
    const float* fc1b  = (const float*)d_in[6];
    const float* outw  = (const float*)d_in[7];
    const float* outb  = (const float*)d_in[8];
    float* out = (float*)d_out;

    prep_kernel<<<(9600 + 255) / 256, 256>>>(cemb, convw);
    conv_kernel<<<(B_ * W_) / 256, 256>>>(inp, wemb, convb);
    fc_kernel<<<B_ / MT, 416>>>(fc1w, fc1b, outw, outb, out);
}

// round 6
// speedup vs baseline: 1.7158x; 1.7158x over previous
#include <cuda_runtime.h>

#define B_    32768
#define W_    5
#define L_    20
#define CE_   32
#define OC_   30
#define WE_   50
#define HID_  100
#define TAGS_ 36
#define TPOS  18

#define SPB   64          // samples per block
#define WPB   320         // words per block (SPB*W_)
#define PO_   150         // pooled feature dim (W_*OC_)
#define PSTR  66          // poolT row stride (floats)
#define KCH   75          // GEMM k chunk

typedef unsigned long long ull;

__device__ float g_Pk[3 * 100 * 32];        // [k][c][ocp*2] conv lookup table
__device__ float g_A[5 * 100 * 104];        // [w][v][j] folded word-emb x fc1w

// ---------------- packed fp32x2 helpers ----------------
__device__ __forceinline__ ull ffma2(ull a, ull b, ull c) {
    ull d;
    asm("fma.rn.f32x2 %0, %1, %2, %3;" : "=l"(d) : "l"(a), "l"(b), "l"(c));
    return d;
}
__device__ __forceinline__ ull add2(ull a, ull b) {
    ull d;
    asm("add.rn.f32x2 %0, %1, %2;" : "=l"(d) : "l"(a), "l"(b));
    return d;
}
__device__ __forceinline__ ull pack2(float lo, float hi) {
    ull r;
    asm("mov.b64 %0, {%1, %2};"
        : "=l"(r) : "r"(__float_as_uint(lo)), "r"(__float_as_uint(hi)));
    return r;
}
__device__ __forceinline__ void unpack2(ull v, float& lo, float& hi) {
    unsigned int a, b;
    asm("mov.b64 {%0, %1}, %2;" : "=r"(a), "=r"(b) : "l"(v));
    lo = __uint_as_float(a);
    hi = __uint_as_float(b);
}

// ---------------- Kernel 0: build P and A tables ----------------
__global__ void prep_kernel(const float* __restrict__ cemb,
                            const float* __restrict__ convw,
                            const float* __restrict__ wemb,
                            const float* __restrict__ fc1w)
{
    const int idx = blockIdx.x * 256 + threadIdx.x;
    if (idx < 9600) {
        // P[k][c][oc] = sum_ce convw[oc][ce][k] * cemb[c][ce]
        const int k  = idx / 3200;
        const int r  = idx - k * 3200;
        const int c  = r >> 5;
        const int oc = r & 31;
        float s = 0.f;
        if (oc < OC_) {
            const float* wr = convw + oc * (CE_ * 3) + k;
            const float* er = cemb + c * CE_;
#pragma unroll
            for (int ce = 0; ce < CE_; ++ce) s = fmaf(wr[ce * 3], er[ce], s);
        }
        g_Pk[idx] = s;
    } else {
        const int e = idx - 9600;
        if (e >= 50000) return;
        // A[w][v][j] = sum_d fc1w[j][w*80+d] * wemb[v][d]
        const int w = e / 10000;
        const int r = e - w * 10000;
        const int v = r / 100;
        const int j = r - v * 100;
        const float* wr = fc1w + j * 400 + w * 80;
        const float* er = wemb + v * WE_;
        float s = 0.f;
#pragma unroll
        for (int d = 0; d < WE_; ++d) s = fmaf(wr[d], er[d], s);
        g_A[(w * 100 + v) * 104 + j] = s;
    }
}

// ---------------- Kernel 1: fully fused main ----------------
__global__ __launch_bounds__(288, 2)
void main_kernel(const int* __restrict__ inp,
                 const float* __restrict__ convb,
                 const float* __restrict__ fc1w, const float* __restrict__ fc1b,
                 const float* __restrict__ outw, const float* __restrict__ outb,
                 const float* __restrict__ wemb,
                 float* __restrict__ out)
{
    extern __shared__ __align__(16) float smem[];
    float* u0    = smem;                 // 9600: P_sh / C_sh chunk / owd (union)
    float* poolT = smem + 9600;          // [150][66] = 9900
    float* hreg  = smem + 19500;         // hacc[64][104] then hT[100][66] (6656)
    int*   wid_sh = (int*)(smem + 26156);        // 320
    float* b_sh   = smem + 26476;                // 104
    float* b2_sh  = smem + 26580;                // 32 (convb)
    float* ob_sh  = smem + 26612;                // 36

    const int tid  = threadIdx.x;
    const int warp = tid >> 5;
    const int lane = tid & 31;
    const int s0   = blockIdx.x * SPB;

    // ---- stage P + small vectors ----
    for (int i = tid; i < 9600; i += 288) u0[i] = g_Pk[i];
    if (tid < 104) b_sh[tid] = (tid < HID_) ? fc1b[tid] : 0.f;
    if (tid < 32)  b2_sh[tid] = (tid < OC_) ? convb[tid] : 0.f;
    if (tid < TAGS_) ob_sh[tid] = outb[tid];
    __syncthreads();

    // ---- Phase 1: pooled conv features (warp = 2 words; half-warps) ----
    {
        const float* P0 = u0;
        const float* P1 = u0 + 3200;
        const float* P2 = u0 + 6400;
        const int half = lane >> 4;
        const int ocp  = lane & 15;

        for (int it = 0; it < 18; ++it) {
            const int wl = it * 18 + warp * 2;      // local word pair base (even)
            if (wl >= WPB) break;
            const int* rowp = inp + (blockIdx.x * WPB + wl) * (1 + L_);
            const int v  = (lane < 21) ? rowp[lane]      : 0;
            const int v2 = (lane < 21) ? rowp[21 + lane] : 0;
            // warp-wide shuffles FIRST (fixes R5 deadlock), then guarded stores
            const int widB = __shfl_sync(0xffffffffu, v2, 0);
            if (lane == 0) wid_sh[wl] = v;              // lane0's v == rowp[0]
            if (lane == 1) wid_sh[wl + 1] = widB;

            ull acc[TPOS];
#pragma unroll
            for (int t = 0; t < TPOS; ++t) acc[t] = 0ull;
#pragma unroll
            for (int l = 0; l < L_; ++l) {
                const int cA = __shfl_sync(0xffffffffu, v,  l + 1);
                const int cB = __shfl_sync(0xffffffffu, v2, l + 1);
                const int c  = half ? cB : cA;
                const int base = c * 32 + ocp * 2;
                const ull x0 = *(const ull*)&P0[base];
                const ull x1 = *(const ull*)&P1[base];
                const ull x2 = *(const ull*)&P2[base];
                if (l < TPOS)            acc[l]     = add2(acc[l],     x0);
                if (l >= 1 && l <= TPOS) acc[l - 1] = add2(acc[l - 1], x1);
                if (l >= 2)              acc[l - 2] = add2(acc[l - 2], x2);
            }
            float m0, m1;
            unpack2(acc[0], m0, m1);
#pragma unroll
            for (int t = 1; t < TPOS; ++t) {
                float a, b;
                unpack2(acc[t], a, b);
                m0 = fmaxf(m0, a);
                m1 = fmaxf(m1, b);
            }
            if (ocp < 15) {
                const int wloc = wl + half;
                const int sl   = wloc / W_;
                const int wis  = wloc - sl * W_;
                const int po   = wis * OC_ + 2 * ocp;
                poolT[po * PSTR + sl]       = m0 + b2_sh[2 * ocp];
                poolT[(po + 1) * PSTR + sl] = m1 + b2_sh[2 * ocp + 1];
            }
        }
    }
    __syncthreads();

    // ---- Phase 2: hacc[s][j] = fc1b[j] + sum_w A[w][wid][j]; stage C chunk 1 ----
    float* hacc = hreg;   // [64][104]
    for (int i = tid; i < SPB * HID_; i += 288) {
        const int s = i / HID_;
        const int j = i - s * HID_;
        float a = b_sh[j];
#pragma unroll
        for (int w = 0; w < W_; ++w) {
            const int vv = wid_sh[s * W_ + w];
            if (vv < 100) {
                a += g_A[(w * 100 + vv) * 104 + j];
            } else {   // cold fallback (ids are <100 by construction)
                const float* wr = fc1w + j * 400 + w * 80;
                const float* er = wemb + vv * WE_;
                for (int d = 0; d < WE_; ++d) a += wr[d] * er[d];
            }
        }
        hacc[s * 104 + j] = a;
    }
    // C chunk 1: C[k][j] = fc1w[j][(k/30)*80 + 50 + k%30], k = 0..74
    for (int i = tid; i < KCH * HID_; i += 288) {
        const int j  = i / KCH;
        const int kk = i - j * KCH;
        const int w  = kk / OC_;
        const int oc = kk - w * OC_;
        u0[kk * 104 + j] = fc1w[j * 400 + w * 80 + 50 + oc];
    }
    __syncthreads();

    // ---- Phase 3: GEMM (h += C @ pooled) ----
    const int jg = tid >> 3;          // 0..24 active (tid<200)
    const int sg = tid & 7;
    const int j0 = jg * 4;
    const int sb = sg * 8;
    const bool active = (tid < 200);

    ull acc[16];
    if (active) {
#pragma unroll
        for (int jj = 0; jj < 4; ++jj)
#pragma unroll
            for (int p = 0; p < 4; ++p)
                acc[jj * 4 + p] = pack2(hacc[(sb + 2 * p) * 104 + j0 + jj],
                                        hacc[(sb + 2 * p + 1) * 104 + j0 + jj]);
    }

#pragma unroll
    for (int ch = 0; ch < 2; ++ch) {
        const int kb = ch * KCH;
        if (ch) {
            __syncthreads();
            for (int i = tid; i < KCH * HID_; i += 288) {
                const int j  = i / KCH;
                const int kk = i - j * KCH;
                const int k  = kb + kk;
                const int w  = k / OC_;
                const int oc = k - w * OC_;
                u0[kk * 104 + j] = fc1w[j * 400 + w * 80 + 50 + oc];
            }
            __syncthreads();
        }
        if (active) {
#pragma unroll 5
            for (int kk = 0; kk < KCH; ++kk) {
                const float4 wq = *(const float4*)&u0[kk * 104 + j0];
                const float* fr = &poolT[(kb + kk) * PSTR + sb];
                const ull f0 = *(const ull*)(fr);
                const ull f1 = *(const ull*)(fr + 2);
                const ull f2 = *(const ull*)(fr + 4);
                const ull f3 = *(const ull*)(fr + 6);
                const ull w0 = pack2(wq.x, wq.x);
                const ull w1 = pack2(wq.y, wq.y);
                const ull w2 = pack2(wq.z, wq.z);
                const ull w3 = pack2(wq.w, wq.w);
                acc[0]  = ffma2(f0, w0, acc[0]);
                acc[4]  = ffma2(f0, w1, acc[4]);
                acc[8]  = ffma2(f0, w2, acc[8]);
                acc[12] = ffma2(f0, w3, acc[12]);
                acc[1]  = ffma2(f1, w0, acc[1]);
                acc[5]  = ffma2(f1, w1, acc[5]);
                acc[9]  = ffma2(f1, w2, acc[9]);
                acc[13] = ffma2(f1, w3, acc[13]);
                acc[2]  = ffma2(f2, w0, acc[2]);
                acc[6]  = ffma2(f2, w1, acc[6]);
                acc[10] = ffma2(f2, w2, acc[10]);
                acc[14] = ffma2(f2, w3, acc[14]);
                acc[3]  = ffma2(f3, w0, acc[3]);
                acc[7]  = ffma2(f3, w1, acc[7]);
                acc[11] = ffma2(f3, w2, acc[11]);
                acc[15] = ffma2(f3, w3, acc[15]);
            }
        }
    }
    __syncthreads();    // all hacc reads done; safe to overwrite hreg as hT

    // ---- tanh + transpose to hT[j][s]; stage owd ----
    float* hT = hreg;   // [100][66]
    if (active) {
#pragma unroll
        for (int jj = 0; jj < 4; ++jj)
#pragma unroll
            for (int p = 0; p < 4; ++p) {
                float a, c;
                unpack2(acc[jj * 4 + p], a, c);
                *(ull*)&hT[(j0 + jj) * PSTR + sb + 2 * p] =
                    pack2(tanhf(a), tanhf(c));
            }
    }
    for (int i = tid; i < TAGS_ * HID_; i += 288) {   // owd[j][2t] duplicated
        const int t = i / HID_;
        const int j = i - t * HID_;
        const float w = outw[i];
        u0[j * 72 + 2 * t]     = w;
        u0[j * 72 + 2 * t + 1] = w;
    }
    __syncthreads();

    // ---- Phase 4: out layer. warp = 4 tags, lane = sample pair ----
    {
        const int t0 = warp * 4;     // 9 warps x 4 = 36 tags
        ull a4[4];
#pragma unroll
        for (int p = 0; p < 4; ++p) a4[p] = 0ull;
#pragma unroll 4
        for (int j = 0; j < HID_; ++j) {
            const ull h = *(const ull*)&hT[j * PSTR + 2 * lane];
            const float* wr = &u0[j * 72 + 2 * t0];
            const ull w01a = *(const ull*)(wr);
            const ull w01b = *(const ull*)(wr + 2);
            const ull w23a = *(const ull*)(wr + 4);
            const ull w23b = *(const ull*)(wr + 6);
            a4[0] = ffma2(h, w01a, a4[0]);
            a4[1] = ffma2(h, w01b, a4[1]);
            a4[2] = ffma2(h, w23a, a4[2]);
            a4[3] = ffma2(h, w23b, a4[3]);
        }
        float r0[4], r1[4];
#pragma unroll
        for (int tt = 0; tt < 4; ++tt) {
            float a, c;
            unpack2(a4[tt], a, c);
            const float bo = ob_sh[t0 + tt];
            r0[tt] = a + bo;
            r1[tt] = c + bo;
        }
        float* op0 = out + (s0 + 2 * lane) * TAGS_ + t0;
        *(float4*)op0           = make_float4(r0[0], r0[1], r0[2], r0[3]);
        *(float4*)(op0 + TAGS_) = make_float4(r1[0], r1[1], r1[2], r1[3]);
    }
}

// ---------------- launch ----------------
extern "C" void kernel_launch(void* const* d_in, const int* in_sizes, int n_in,
                              void* d_out, int out_size)
{
    const int*   inp   = (const int*)  d_in[0];
    const float* wemb  = (const float*)d_in[1];
    const float* cemb  = (const float*)d_in[2];
    const float* convw = (const float*)d_in[3];
    const float* convb = (const float*)d_in[4];
    const float* fc1w  = (const float*)d_in[5];
    const float* fc1b  = (const float*)d_in[6];
    const float* outw  = (const float*)d_in[7];
    const float* outb  = (const float*)d_in[8];
    float* out = (float*)d_out;

    const int smem_bytes = 26648 * 4;   // ~106.6 KB
    cudaFuncSetAttribute(main_kernel,
                         cudaFuncAttributeMaxDynamicSharedMemorySize, smem_bytes);

    prep_kernel<<<(9600 + 50000 + 255) / 256, 256>>>(cemb, convw, wemb, fc1w);
    main_kernel<<<B_ / SPB, 288, smem_bytes>>>(inp, convb, fc1w, fc1b,
                                               outw, outb, wemb, out);
}

// round 7
// speedup vs baseline: 1.8613x; 1.0848x over previous
#include <cuda_runtime.h>

#define B_    32768
#define W_    5
#define L_    20
#define CE_   32
#define OC_   30
#define WE_   50
#define HID_  100
#define TAGS_ 36
#define TPOS  18

#define SPB   64
#define WPB   320
#define PSTR  68          // poolT row stride (16B aligned rows)
#define NT    320         // threads per block

typedef unsigned long long ull;

__device__ float g_Pk[3 * 100 * 32];     // [k][c][oc] (oc padded to 32, zeros)
__device__ float g_A[5 * 100 * 104];     // [w][v][j]  folded word-emb x fc1w

// ---------------- packed fp32x2 helpers ----------------
__device__ __forceinline__ ull ffma2(ull a, ull b, ull c) {
    ull d;
    asm("fma.rn.f32x2 %0, %1, %2, %3;" : "=l"(d) : "l"(a), "l"(b), "l"(c));
    return d;
}
__device__ __forceinline__ ull add2(ull a, ull b) {
    ull d;
    asm("add.rn.f32x2 %0, %1, %2;" : "=l"(d) : "l"(a), "l"(b));
    return d;
}
__device__ __forceinline__ ull pack2(float lo, float hi) {
    ull r;
    asm("mov.b64 %0, {%1, %2};"
        : "=l"(r) : "r"(__float_as_uint(lo)), "r"(__float_as_uint(hi)));
    return r;
}
__device__ __forceinline__ void unpack2(ull v, float& lo, float& hi) {
    unsigned int a, b;
    asm("mov.b64 {%0, %1}, %2;" : "=r"(a), "=r"(b) : "l"(v));
    lo = __uint_as_float(a);
    hi = __uint_as_float(b);
}

// ---------------- Kernel 0: build P and A tables ----------------
__global__ void prep_kernel(const float* __restrict__ cemb,
                            const float* __restrict__ convw,
                            const float* __restrict__ wemb,
                            const float* __restrict__ fc1w)
{
    const int idx = blockIdx.x * 256 + threadIdx.x;
    if (idx < 9600) {
        const int k  = idx / 3200;
        const int r  = idx - k * 3200;
        const int c  = r >> 5;
        const int oc = r & 31;
        float s = 0.f;
        if (oc < OC_) {
            const float* wr = convw + oc * (CE_ * 3) + k;
            const float* er = cemb + c * CE_;
            float p0 = 0.f, p1 = 0.f, p2 = 0.f, p3 = 0.f;
#pragma unroll
            for (int ce = 0; ce < CE_; ce += 4) {
                p0 = fmaf(wr[(ce + 0) * 3], er[ce + 0], p0);
                p1 = fmaf(wr[(ce + 1) * 3], er[ce + 1], p1);
                p2 = fmaf(wr[(ce + 2) * 3], er[ce + 2], p2);
                p3 = fmaf(wr[(ce + 3) * 3], er[ce + 3], p3);
            }
            s = (p0 + p1) + (p2 + p3);
        }
        g_Pk[idx] = s;
    } else {
        const int e = idx - 9600;
        if (e >= 50000) return;
        const int w = e / 10000;
        const int r = e - w * 10000;
        const int v = r / 100;
        const int j = r - v * 100;
        const float* wr = fc1w + j * 400 + w * 80;
        const float* er = wemb + v * WE_;
        float p0 = 0.f, p1 = 0.f, p2 = 0.f, p3 = 0.f;
#pragma unroll
        for (int d = 0; d < 48; d += 4) {
            p0 = fmaf(wr[d + 0], er[d + 0], p0);
            p1 = fmaf(wr[d + 1], er[d + 1], p1);
            p2 = fmaf(wr[d + 2], er[d + 2], p2);
            p3 = fmaf(wr[d + 3], er[d + 3], p3);
        }
        p0 = fmaf(wr[48], er[48], p0);
        p1 = fmaf(wr[49], er[49], p1);
        g_A[(w * 100 + v) * 104 + j] = (p0 + p1) + (p2 + p3);
    }
}

// ---------------- Kernel 1: fully fused main ----------------
__global__ __launch_bounds__(NT, 2)
void main_kernel(const int* __restrict__ inp,
                 const float* __restrict__ convb,
                 const float* __restrict__ fc1w, const float* __restrict__ fc1b,
                 const float* __restrict__ outw, const float* __restrict__ outb,
                 const float* __restrict__ wemb,
                 float* __restrict__ out)
{
    extern __shared__ __align__(16) float smem[];
    float* u0    = smem;                  // 9600: P / C-dup chunk (40x208) / owd (100x72)
    float* poolT = smem + 9600;           // [150][68] = 10200 ; later hT[100][68]
    int*   idbuf  = (int*)(smem + 19800); // [10][48] = 480
    int*   wid_sh = (int*)(smem + 20280); // 320
    float* b_sh   = smem + 20600;         // 104 (fc1b)
    float* cb2    = smem + 20704;         // 32  (convb)
    float* ob_sh  = smem + 20736;         // 36  (outb)

    const int tid  = threadIdx.x;
    const int warp = tid >> 5;
    const int lane = tid & 31;
    const int s0   = blockIdx.x * SPB;

    // ---- stage P + small vectors ----
    for (int i = tid; i < 9600; i += NT) u0[i] = g_Pk[i];
    if (tid < 104) b_sh[tid] = (tid < HID_) ? fc1b[tid] : 0.f;
    if (tid < 32)  cb2[tid]  = (tid < OC_) ? convb[tid] : 0.f;
    if (tid < TAGS_) ob_sh[tid] = outb[tid];
    __syncthreads();

    // ---- Phase 1: pooled conv features (10 warps x 2 words/iter, 16 iters) ----
    {
        const float* P0 = u0;
        const float* P1 = u0 + 3200;
        const float* P2 = u0 + 6400;
        const int half = lane >> 4;
        const int ocp  = lane & 15;
        int* wb = idbuf + warp * 48;

        for (int it = 0; it < 16; ++it) {
            const int wl = it * 20 + warp * 2;
            const int* rowp = inp + (blockIdx.x * WPB + wl) * (1 + L_);
            int a = 0, bb = 0;
            if (lane < 21) { a = rowp[lane]; bb = rowp[21 + lane]; }
            if (lane < 21) { wb[lane] = a; wb[21 + lane] = bb; }
            __syncwarp();
            if (lane == 0) { wid_sh[wl] = a; wid_sh[wl + 1] = bb; }

            const int* myid = wb + half * 21 + 1;
            int ca = myid[0], cb_ = myid[1];
            ull acc[TPOS];
#pragma unroll
            for (int t = 0; t < TPOS; ++t) {
                const int cc = myid[t + 2];
                const ull x0 = *(const ull*)&P0[ca  * 32 + ocp * 2];
                const ull x1 = *(const ull*)&P1[cb_ * 32 + ocp * 2];
                const ull x2 = *(const ull*)&P2[cc  * 32 + ocp * 2];
                acc[t] = add2(add2(x0, x1), x2);
                ca = cb_; cb_ = cc;
            }

            float m0, m1;
            unpack2(acc[0], m0, m1);
#pragma unroll
            for (int t = 1; t < TPOS; ++t) {
                float x, y;
                unpack2(acc[t], x, y);
                m0 = fmaxf(m0, x);
                m1 = fmaxf(m1, y);
            }
            if (ocp < 15) {
                const int wloc = wl + half;
                const int sl   = wloc / W_;
                const int wis  = wloc - sl * W_;
                const int po   = wis * OC_ + 2 * ocp;
                poolT[po * PSTR + sl]       = m0 + cb2[2 * ocp];
                poolT[(po + 1) * PSTR + sl] = m1 + cb2[2 * ocp + 1];
            }
            __syncwarp();   // wb reused next iter
        }
    }
    __syncthreads();

    // ---- Phase 2: init GEMM accs from A table; stage C chunk 0 ----
    const int jg = tid >> 3;
    const int sg = tid & 7;
    const int j0 = jg * 4;
    const int sb = sg * 8;
    const bool active = (tid < 200);
    float* wsh = u0;    // C duplicated [kk][2j], stride 208

    // chunk staging lambda-ish macro
    #define STAGE_C(KB, KCNT)                                                   \
        for (int i = tid; i < (KCNT) * HID_; i += NT) {                         \
            const int kk = i % (KCNT);                                          \
            const int j  = i / (KCNT);                                          \
            const int kg = (KB) + kk;                                           \
            const int w  = kg / OC_;                                            \
            const int oc = kg - w * OC_;                                        \
            const float wv = fc1w[j * 400 + w * 80 + 50 + oc];                  \
            *(ull*)&wsh[kk * 208 + 2 * j] = pack2(wv, wv);                      \
        }

    STAGE_C(0, 40)

    ull acc[16];
    if (active) {
        const float4 bias4 = *(const float4*)&b_sh[j0];
#pragma unroll
        for (int p = 0; p < 4; ++p) {
            const int sA = sb + 2 * p;
            float4 a4 = bias4, b4 = bias4;
#pragma unroll
            for (int w = 0; w < W_; ++w) {
                const int vA = wid_sh[sA * W_ + w];
                const int vB = wid_sh[(sA + 1) * W_ + w];
                if (vA < 100) {
                    const float4 t = *(const float4*)&g_A[(w * 100 + vA) * 104 + j0];
                    a4.x += t.x; a4.y += t.y; a4.z += t.z; a4.w += t.w;
                } else {
                    const float* wr = fc1w + w * 80;
                    const float* er = wemb + vA * WE_;
                    for (int d = 0; d < WE_; ++d) {
                        const float e = er[d];
                        a4.x += wr[(j0+0)*400 + d] * e;
                        a4.y += wr[(j0+1)*400 + d] * e;
                        a4.z += wr[(j0+2)*400 + d] * e;
                        a4.w += wr[(j0+3)*400 + d] * e;
                    }
                }
                if (vB < 100) {
                    const float4 t = *(const float4*)&g_A[(w * 100 + vB) * 104 + j0];
                    b4.x += t.x; b4.y += t.y; b4.z += t.z; b4.w += t.w;
                } else {
                    const float* wr = fc1w + w * 80;
                    const float* er = wemb + vB * WE_;
                    for (int d = 0; d < WE_; ++d) {
                        const float e = er[d];
                        b4.x += wr[(j0+0)*400 + d] * e;
                        b4.y += wr[(j0+1)*400 + d] * e;
                        b4.z += wr[(j0+2)*400 + d] * e;
                        b4.w += wr[(j0+3)*400 + d] * e;
                    }
                }
            }
            acc[p]      = pack2(a4.x, b4.x);
            acc[4 + p]  = pack2(a4.y, b4.y);
            acc[8 + p]  = pack2(a4.z, b4.z);
            acc[12 + p] = pack2(a4.w, b4.w);
        }
    }
    __syncthreads();

    // ---- Phase 3: GEMM over 4 chunks (40,40,40,30) ----
#pragma unroll
    for (int ch = 0; ch < 4; ++ch) {
        const int kb   = ch * 40;
        const int kcnt = (ch == 3) ? 30 : 40;
        if (active) {
            for (int kk = 0; kk < kcnt; ++kk) {
                const float* wrow = &wsh[kk * 208 + 2 * j0];
                const ulonglong2 wa = *(const ulonglong2*)(wrow);
                const ulonglong2 wbv = *(const ulonglong2*)(wrow + 4);
                const float* fr = &poolT[(kb + kk) * PSTR + sb];
                const ulonglong2 fA = *(const ulonglong2*)(fr);
                const ulonglong2 fB = *(const ulonglong2*)(fr + 4);
                acc[0]  = ffma2(fA.x, wa.x,  acc[0]);
                acc[4]  = ffma2(fA.x, wa.y,  acc[4]);
                acc[8]  = ffma2(fA.x, wbv.x, acc[8]);
                acc[12] = ffma2(fA.x, wbv.y, acc[12]);
                acc[1]  = ffma2(fA.y, wa.x,  acc[1]);
                acc[5]  = ffma2(fA.y, wa.y,  acc[5]);
                acc[9]  = ffma2(fA.y, wbv.x, acc[9]);
                acc[13] = ffma2(fA.y, wbv.y, acc[13]);
                acc[2]  = ffma2(fB.x, wa.x,  acc[2]);
                acc[6]  = ffma2(fB.x, wa.y,  acc[6]);
                acc[10] = ffma2(fB.x, wbv.x, acc[10]);
                acc[14] = ffma2(fB.x, wbv.y, acc[14]);
                acc[3]  = ffma2(fB.y, wa.x,  acc[3]);
                acc[7]  = ffma2(fB.y, wa.y,  acc[7]);
                acc[11] = ffma2(fB.y, wbv.x, acc[11]);
                acc[15] = ffma2(fB.y, wbv.y, acc[15]);
            }
        }
        if (ch < 3) {
            __syncthreads();
            STAGE_C(kb + 40, (ch == 2) ? 30 : 40)
            __syncthreads();
        }
    }
    __syncthreads();

    // ---- tanh -> hT[j][s] (overlays poolT); stage owd (overlays u0) ----
    float* hT = poolT;
    if (active) {
#pragma unroll
        for (int jj = 0; jj < 4; ++jj)
#pragma unroll
            for (int p = 0; p < 4; ++p) {
                float a, c;
                unpack2(acc[jj * 4 + p], a, c);
                *(ull*)&hT[(j0 + jj) * PSTR + sb + 2 * p] = pack2(tanhf(a), tanhf(c));
            }
    }
    for (int i = tid; i < TAGS_ * HID_; i += NT) {
        const int t = i / HID_;
        const int j = i - t * HID_;
        const float w = outw[i];
        u0[j * 72 + 2 * t]     = w;
        u0[j * 72 + 2 * t + 1] = w;
    }
    __syncthreads();

    // ---- Phase 4: out layer (9 warps of 10; warp = 4 tags, lane = sample pair) ----
    if (warp < 9) {
        const int t0 = warp * 4;
        ull a4[4];
#pragma unroll
        for (int p = 0; p < 4; ++p) a4[p] = 0ull;
#pragma unroll 4
        for (int j = 0; j < HID_; ++j) {
            const ull h = *(const ull*)&hT[j * PSTR + 2 * lane];
            const float* wr = &u0[j * 72 + 2 * t0];
            const ulonglong2 w01 = *(const ulonglong2*)(wr);
            const ulonglong2 w23 = *(const ulonglong2*)(wr + 4);
            a4[0] = ffma2(h, w01.x, a4[0]);
            a4[1] = ffma2(h, w01.y, a4[1]);
            a4[2] = ffma2(h, w23.x, a4[2]);
            a4[3] = ffma2(h, w23.y, a4[3]);
        }
        float r0[4], r1[4];
#pragma unroll
        for (int tt = 0; tt < 4; ++tt) {
            float a, c;
            unpack2(a4[tt], a, c);
            const float bo = ob_sh[t0 + tt];
            r0[tt] = a + bo;
            r1[tt] = c + bo;
        }
        float* op0 = out + (s0 + 2 * lane) * TAGS_ + t0;
        *(float4*)op0           = make_float4(r0[0], r0[1], r0[2], r0[3]);
        *(float4*)(op0 + TAGS_) = make_float4(r1[0], r1[1], r1[2], r1[3]);
    }
}

// ---------------- launch ----------------
extern "C" void kernel_launch(void* const* d_in, const int* in_sizes, int n_in,
                              void* d_out, int out_size)
{
    const int*   inp   = (const int*)  d_in[0];
    const float* wemb  = (const float*)d_in[1];
    const float* cemb  = (const float*)d_in[2];
    const float* convw = (const float*)d_in[3];
    const float* convb = (const float*)d_in[4];
    const float* fc1w  = (const float*)d_in[5];
    const float* fc1b  = (const float*)d_in[6];
    const float* outw  = (const float*)d_in[7];
    const float* outb  = (const float*)d_in[8];
    float* out = (float*)d_out;

    const int smem_bytes = 20772 * 4 + 256;   // ~83.3 KB
    cudaFuncSetAttribute(main_kernel,
                         cudaFuncAttributeMaxDynamicSharedMemorySize, smem_bytes);

    prep_kernel<<<(9600 + 50000 + 255) / 256, 256>>>(cemb, convw, wemb, fc1w);
    main_kernel<<<B_ / SPB, NT, smem_bytes>>>(inp, convb, fc1w, fc1b,
                                              outw, outb, wemb, out);
}